// round 4
// baseline (speedup 1.0000x reference)
#include <cuda_runtime.h>
#include <math.h>

#define NS 128      // hidden states
#define DD 128      // observation dim
#define BB 16       // batch
#define TT 4096     // sequence length
#define LOG2PI_F 1.8378770664093453f

// ---- device scratch (no allocs allowed) ----
__device__ float g_W[NS * NS];                    // softmax(transition) row-major
__device__ __align__(16) float2 g_Wp[NS * 64];    // g_Wp[j*64+k] = (W[2k][j], W[2k+1][j])
__device__ __align__(16) float2 g_cAB[NS * DD];   // (cA, cB) = (-0.5/var, mu/var)
__device__ float g_k[NS];
__device__ float g_logpi[NS];
__device__ float g_E[BB * TT * NS];               // emission logprobs [B][T][N]
__device__ float g_partial[BB];

// ---- packed f32x2 helpers ----
__device__ __forceinline__ void ffma2(unsigned long long& acc,
                                      unsigned long long ab,
                                      unsigned long long w) {
    asm("fma.rn.f32x2 %0, %1, %2, %0;" : "+l"(acc) : "l"(ab), "l"(w));
}
__device__ __forceinline__ float pairsum(unsigned long long a) {
    return __uint_as_float((unsigned)a) + __uint_as_float((unsigned)(a >> 32));
}
__device__ __forceinline__ float warp_max(float v) {
    v = fmaxf(v, __shfl_xor_sync(0xffffffffu, v, 16));
    v = fmaxf(v, __shfl_xor_sync(0xffffffffu, v, 8));
    v = fmaxf(v, __shfl_xor_sync(0xffffffffu, v, 4));
    v = fmaxf(v, __shfl_xor_sync(0xffffffffu, v, 2));
    v = fmaxf(v, __shfl_xor_sync(0xffffffffu, v, 1));
    return v;
}

// ============================================================
// Setup: softmax(transition) -> W (+paired transpose), log_softmax(priors),
// emission coefficient pairs
// ============================================================
__global__ void setup_kernel(const float* __restrict__ trans,
                             const float* __restrict__ priors,
                             const float* __restrict__ means,
                             const float* __restrict__ scales) {
    int n = threadIdx.x;  // 0..127
    __shared__ float spri[NS];
    spri[n] = priors[n];
    __syncthreads();

    float mx = -1e30f;
    for (int i = 0; i < NS; i++) mx = fmaxf(mx, spri[i]);
    float se = 0.f;
    for (int i = 0; i < NS; i++) se += expf(spri[i] - mx);
    g_logpi[n] = spri[n] - mx - logf(se);

    // W row n = softmax over j of transition[n][:]
    float rmx = -1e30f;
    for (int j = 0; j < NS; j++) rmx = fmaxf(rmx, trans[n * NS + j]);
    float rs = 0.f;
    for (int j = 0; j < NS; j++) rs += expf(trans[n * NS + j] - rmx);
    float inv_rs = 1.0f / rs;
    for (int j = 0; j < NS; j++)
        g_W[n * NS + j] = expf(trans[n * NS + j] - rmx) * inv_rs;

    // emission coefficient pairs for state n
    float c = 0.f;
    for (int d = 0; d < DD; d++) {
        float x = scales[n * DD + d];
        float sp = (x > 20.f) ? x : log1pf(expf(x));
        float var = sp + 1e-6f;
        float inv = 1.0f / var;
        float mu = means[n * DD + d];
        g_cAB[n * DD + d] = make_float2(-0.5f * inv, mu * inv);
        c += mu * mu * inv + logf(var);
    }
    g_k[n] = -0.5f * (c + (float)DD * LOG2PI_F);

    __syncthreads();  // orders g_W writes (global, same block) before reads

    // paired transpose: thread j owns column j
    for (int k = 0; k < 64; k++)
        g_Wp[n * 64 + k] = make_float2(g_W[(2 * k) * NS + n],
                                       g_W[(2 * k + 1) * NS + n]);
}

// ============================================================
// Emission: E[b][t][n] = k_n + sum_d (x^2, x) . (cA, cB)   via fma.rn.f32x2
// ============================================================
#define TROWS 16
__global__ __launch_bounds__(128) void emis_kernel(const float* __restrict__ X) {
    __shared__ __align__(16) float2 sXQ[TROWS * DD];  // (x^2, x)
    int n = threadIdx.x;
    int blk = blockIdx.x;
    int b = blk >> 8;                 // T/TROWS = 256
    int tc = blk & 255;
    const float* Xp = X + ((size_t)b * TT + (size_t)tc * TROWS) * DD;

    for (int k = n; k < TROWS * DD; k += 128) {
        float x = Xp[k];
        sXQ[k] = make_float2(x * x, x);
    }
    __syncthreads();

    unsigned long long acc[TROWS];
#pragma unroll
    for (int t = 0; t < TROWS; t++) acc[t] = 0ULL;

    for (int dc = 0; dc < 4; dc++) {
        // 32 coefficient pairs for this d-chunk into registers
        unsigned long long cw[32];
        const unsigned long long* c8 =
            (const unsigned long long*)(g_cAB + n * DD + dc * 32);
#pragma unroll
        for (int q = 0; q < 32; q++) cw[q] = c8[q];

#pragma unroll
        for (int t = 0; t < TROWS; t++) {
            const ulonglong2* x2 = (const ulonglong2*)(sXQ + t * DD + dc * 32);
            unsigned long long a0 = 0ULL, a1 = 0ULL;
#pragma unroll
            for (int q = 0; q < 8; q++) {
                ulonglong2 v0 = x2[2 * q];
                ulonglong2 v1 = x2[2 * q + 1];
                ffma2(a0, v0.x, cw[4 * q + 0]);
                ffma2(a0, v0.y, cw[4 * q + 1]);
                ffma2(a1, v1.x, cw[4 * q + 2]);
                ffma2(a1, v1.y, cw[4 * q + 3]);
            }
            asm("add.rn.f32x2 %0, %0, %1;" : "+l"(acc[t]) : "l"(a0));
            asm("add.rn.f32x2 %0, %0, %1;" : "+l"(acc[t]) : "l"(a1));
        }
    }
    float kn = g_k[n];
    float* Eout = g_E + ((size_t)b * TT + (size_t)tc * TROWS) * NS;
#pragma unroll
    for (int t = 0; t < TROWS; t++) Eout[t * NS + n] = kn + pairsum(acc[t]);
}

// ============================================================
// Forward recursion: 1 CTA per batch, 128 threads (thread = state j)
// W column in registers as (i, i+1) pairs; matvec via fma.rn.f32x2.
// ============================================================
__global__ __launch_bounds__(128, 1) void forward_kernel() {
    int b = blockIdx.x;
    int j = threadIdx.x;
    int w = j >> 5;
    int lane = j & 31;

    // W column j as 64 packed pairs
    unsigned long long Wc[64];
    const unsigned long long* Wp = (const unsigned long long*)(g_Wp + j * 64);
#pragma unroll
    for (int k = 0; k < 64; k++) Wc[k] = Wp[k];

    __shared__ __align__(16) float sp[2][NS];
    __shared__ float swm[2][4];

    const float* Eb = g_E + (size_t)b * TT * NS;

    float alpha = g_logpi[j] + Eb[j];       // t = 0
    float eA = Eb[1 * NS + j];
    float eB = Eb[2 * NS + j];

    for (int t = 1; t < TT; ++t) {
        int tp = (t + 2 < TT) ? (t + 2) : (TT - 1);
        float enew = __ldg(Eb + tp * NS + j);

        float wm = warp_max(alpha);
        float p = __expf(alpha - wm);
        int pb = t & 1;
        sp[pb][j] = p;
        if (lane == 0) swm[pb][w] = wm;
        __syncthreads();

        float m = fmaxf(fmaxf(swm[pb][0], swm[pb][1]),
                        fmaxf(swm[pb][2], swm[pb][3]));

        // matvec: s = sum_w exp(wmax_w - m) * sum_{i in warp w} p_i * W[i][j]
        float s = 0.f;
        const ulonglong2* pv = (const ulonglong2*)sp[pb];
#pragma unroll
        for (int wg = 0; wg < 4; ++wg) {
            unsigned long long a0 = 0ULL, a1 = 0ULL;
#pragma unroll
            for (int q = 0; q < 4; q++) {
                ulonglong2 v0 = pv[wg * 8 + 2 * q];
                ulonglong2 v1 = pv[wg * 8 + 2 * q + 1];
                ffma2(a0, v0.x, Wc[wg * 16 + 4 * q + 0]);
                ffma2(a0, v0.y, Wc[wg * 16 + 4 * q + 1]);
                ffma2(a1, v1.x, Wc[wg * 16 + 4 * q + 2]);
                ffma2(a1, v1.y, Wc[wg * 16 + 4 * q + 3]);
            }
            float f = __expf(swm[pb][wg] - m);
            s = fmaf(f, pairsum(a0) + pairsum(a1), s);
        }

        alpha = eA + m + __logf(s);
        eA = eB;
        eB = enew;
        // double-buffered sp/swm: no second barrier needed
    }

    // final logsumexp over alpha
    __syncthreads();
    float wm = warp_max(alpha);
    if (lane == 0) swm[0][w] = wm;
    __syncthreads();
    float m = fmaxf(fmaxf(swm[0][0], swm[0][1]), fmaxf(swm[0][2], swm[0][3]));
    float p = __expf(alpha - m);
    p += __shfl_xor_sync(0xffffffffu, p, 16);
    p += __shfl_xor_sync(0xffffffffu, p, 8);
    p += __shfl_xor_sync(0xffffffffu, p, 4);
    p += __shfl_xor_sync(0xffffffffu, p, 2);
    p += __shfl_xor_sync(0xffffffffu, p, 1);
    if (lane == 0) sp[0][w] = p;
    __syncthreads();
    if (j == 0) {
        float s = sp[0][0] + sp[0][1] + sp[0][2] + sp[0][3];
        g_partial[b] = m + __logf(s);
    }
}

__global__ void final_kernel(float* __restrict__ out) {
    if (threadIdx.x == 0) {
        float s = 0.f;
        for (int b = 0; b < BB; b++) s += g_partial[b];
        out[0] = s;
    }
}

// ============================================================
extern "C" void kernel_launch(void* const* d_in, const int* in_sizes, int n_in,
                              void* d_out, int out_size) {
    const float* X      = (const float*)d_in[0];  // [B,T,D]
    const float* trans  = (const float*)d_in[1];  // [N,N]
    const float* priors = (const float*)d_in[2];  // [N]
    const float* means  = (const float*)d_in[3];  // [N,D]
    const float* scales = (const float*)d_in[4];  // [N,D]
    float* out = (float*)d_out;

    setup_kernel<<<1, 128>>>(trans, priors, means, scales);
    emis_kernel<<<(BB * TT) / TROWS, 128>>>(X);
    forward_kernel<<<BB, 128>>>();
    final_kernel<<<1, 32>>>(out);
}